// round 1
// baseline (speedup 1.0000x reference)
#include <cuda_runtime.h>
#include <cstdint>

#define IN_DIM   128
#define OUT_DIM  128
#define BATCH    8192
#define KTOT     384          // 3 powers * 128 inputs, k = pw*128 + j
#define KT       32           // k-tile staged in smem
#define NTILES   (KTOT / KT)  // 12
#define BTILE    64           // batch rows per CTA
#define THREADS  256

// Transposed coefficients: g_Ct[k*128 + o] = coeff[(o*128 + j)*4 + pw + 1], k = pw*128+j
__device__ float g_Ct[KTOT * OUT_DIM];
__device__ float g_Bias[OUT_DIM];

// ---------------- prologue: transpose coeff + compute bias ----------------
__global__ void prep_kernel(const float* __restrict__ coeff) {
    if (blockIdx.x < 192) {
        int idx = blockIdx.x * 256 + threadIdx.x;   // [0, 49152)
        int k = idx >> 7;          // 0..383
        int o = idx & 127;
        int pw = k >> 7;           // 0..2
        int j  = k & 127;
        g_Ct[idx] = coeff[(((o << 7) + j) << 2) + pw + 1];
    } else {
        int o = threadIdx.x;
        if (o < OUT_DIM) {
            float s = 0.f;
#pragma unroll 16
            for (int j = 0; j < IN_DIM; ++j)
                s += coeff[(((o << 7) + j) << 2)];
            g_Bias[o] = s;
        }
    }
}

// ---------------- packed fp32x2 helpers ----------------
#define FMA2(d, a, b) \
    asm("fma.rn.f32x2 %0, %1, %2, %0;" : "+l"(d) : "l"(a), "l"(b))

__device__ __forceinline__ unsigned long long pack_dup(float v) {
    unsigned long long r;
    unsigned int u = __float_as_uint(v);
    asm("mov.b64 %0, {%1, %1};" : "=l"(r) : "r"(u));
    return r;
}

__device__ __forceinline__ float2 unpack2(unsigned long long v) {
    unsigned int lo, hi;
    asm("mov.b64 {%0, %1}, %2;" : "=r"(lo), "=r"(hi) : "l"(v));
    return make_float2(__uint_as_float(lo), __uint_as_float(hi));
}

// ---------------- main kernel ----------------
// smem: A_s[KTOT][BTILE] (x powers, 96KB) + C_s[2][KT][128] (coeff tiles, 32KB)
__global__ void __launch_bounds__(THREADS, 1)
kan_kernel(const float* __restrict__ x, float* __restrict__ out) {
    extern __shared__ float smem[];
    float* A_s = smem;                       // [KTOT][BTILE]
    float* C_s = smem + KTOT * BTILE;        // [2][KT][128]

    const int tid = threadIdx.x;
    const int tx  = tid & 15;                // output group: o in {4tx..4tx+3} U {64+4tx..}
    const int ty  = tid >> 4;                // row group: rows 4ty..4ty+3
    const int b0  = blockIdx.x * BTILE;

    // ---- build A_s: A_s[(pw*128+j)*64 + r] = x[b0+r][j]^(pw+1) ----
    // consecutive tid -> consecutive r: conflict-free STS
#pragma unroll
    for (int it = 0; it < (BTILE * IN_DIM) / THREADS; ++it) {   // 32 iters
        int idx = tid + it * THREADS;
        int r = idx & (BTILE - 1);
        int j = idx >> 6;
        float v  = x[(b0 + r) * IN_DIM + j];
        float v2 = v * v;
        A_s[(j)       * BTILE + r] = v;
        A_s[(128 + j) * BTILE + r] = v2;
        A_s[(256 + j) * BTILE + r] = v2 * v;
    }

    // ---- load first C tile (coalesced via float4) ----
    float4 pf[4];
    {
        const float4* src = reinterpret_cast<const float4*>(g_Ct);
#pragma unroll
        for (int i = 0; i < 4; ++i) pf[i] = src[tid + i * THREADS];
        float4* dst = reinterpret_cast<float4*>(C_s);
#pragma unroll
        for (int i = 0; i < 4; ++i) dst[tid + i * THREADS] = pf[i];
    }
    __syncthreads();

    // accumulators: 4 rows x 4 output-pairs, each packed f32x2
    unsigned long long acc[4][4];
#pragma unroll
    for (int r = 0; r < 4; ++r)
#pragma unroll
        for (int p = 0; p < 4; ++p) acc[r][p] = 0ull;

    for (int t = 0; t < NTILES; ++t) {
        // prefetch next C tile into registers (overlaps with compute)
        if (t + 1 < NTILES) {
            const float4* src =
                reinterpret_cast<const float4*>(g_Ct + (t + 1) * KT * OUT_DIM);
#pragma unroll
            for (int i = 0; i < 4; ++i) pf[i] = src[tid + i * THREADS];
        }

        const float* Cc = C_s + (t & 1) * (KT * OUT_DIM);
        const float* Ak = A_s + t * KT * BTILE;

#pragma unroll
        for (int kk = 0; kk < KT; ++kk) {
            // A: 4 rows for this thread (broadcast within warp -> 1 wavefront)
            float4 a4 = *reinterpret_cast<const float4*>(Ak + kk * BTILE + (ty << 2));
            unsigned long long ad[4];
            ad[0] = pack_dup(a4.x);
            ad[1] = pack_dup(a4.y);
            ad[2] = pack_dup(a4.z);
            ad[3] = pack_dup(a4.w);

            // C: 8 outputs = 4 packed pairs; stride-16B lanes -> 2 wf per LDS.128
            ulonglong2 cA = *reinterpret_cast<const ulonglong2*>(Cc + kk * OUT_DIM + (tx << 2));
            ulonglong2 cB = *reinterpret_cast<const ulonglong2*>(Cc + kk * OUT_DIM + 64 + (tx << 2));

#pragma unroll
            for (int r = 0; r < 4; ++r) {
                FMA2(acc[r][0], ad[r], cA.x);
                FMA2(acc[r][1], ad[r], cA.y);
                FMA2(acc[r][2], ad[r], cB.x);
                FMA2(acc[r][3], ad[r], cB.y);
            }
        }

        __syncthreads();   // everyone done reading C_s[(t-1)&1] long ago; safe to overwrite
        if (t + 1 < NTILES) {
            float4* dst = reinterpret_cast<float4*>(C_s + ((t + 1) & 1) * (KT * OUT_DIM));
#pragma unroll
            for (int i = 0; i < 4; ++i) dst[tid + i * THREADS] = pf[i];
        }
        __syncthreads();   // stores visible before next compute
    }

    // ---- epilogue: add bias (degree-0 term), write out ----
    float bias[8];
    *reinterpret_cast<float4*>(&bias[0]) =
        *reinterpret_cast<const float4*>(&g_Bias[tx << 2]);
    *reinterpret_cast<float4*>(&bias[4]) =
        *reinterpret_cast<const float4*>(&g_Bias[64 + (tx << 2)]);

#pragma unroll
    for (int r = 0; r < 4; ++r) {
        int b = b0 + (ty << 2) + r;
        float2 v0 = unpack2(acc[r][0]);
        float2 v1 = unpack2(acc[r][1]);
        float2 v2 = unpack2(acc[r][2]);
        float2 v3 = unpack2(acc[r][3]);
        float4 o1 = make_float4(v0.x + bias[0], v0.y + bias[1],
                                v1.x + bias[2], v1.y + bias[3]);
        float4 o2 = make_float4(v2.x + bias[4], v2.y + bias[5],
                                v3.x + bias[6], v3.y + bias[7]);
        *reinterpret_cast<float4*>(out + b * OUT_DIM + (tx << 2))      = o1;
        *reinterpret_cast<float4*>(out + b * OUT_DIM + 64 + (tx << 2)) = o2;
    }
}

// ---------------- launch ----------------
extern "C" void kernel_launch(void* const* d_in, const int* in_sizes, int n_in,
                              void* d_out, int out_size) {
    const float* x     = (const float*)d_in[0];   // [8192, 128] fp32
    const float* coeff = (const float*)d_in[1];   // [16384, 4] fp32
    float* out = (float*)d_out;                   // [8192, 128] fp32

    const int smem_bytes = (KTOT * BTILE + 2 * KT * OUT_DIM) * (int)sizeof(float); // 128KB
    static bool attr_set = false;
    // cudaFuncSetAttribute is idempotent & not a stream op (capture-safe);
    // call unconditionally to keep kernel_launch deterministic.
    (void)attr_set;
    cudaFuncSetAttribute(kan_kernel, cudaFuncAttributeMaxDynamicSharedMemorySize, smem_bytes);

    prep_kernel<<<193, 256>>>(coeff);
    kan_kernel<<<BATCH / BTILE, THREADS, smem_bytes>>>(x, out);
}

// round 3
// speedup vs baseline: 2.2121x; 2.2121x over previous
#include <cuda_runtime.h>
#include <cuda_bf16.h>
#include <cstdint>

// Problem dims
#define BATCH    8192
#define DIM      128          // in_dim == out_dim
#define KTOT     384          // 3 powers * 128 inputs, k = pw*128 + j
#define KC       64           // K per chunk
#define NCHUNK   6
#define MTILE    64           // batch rows per CTA
#define THREADS  256          // 8 warps: 2 (m) x 4 (n)
#define NCTA     (BATCH / MTILE)   // 128

// Pre-split coefficients, [o][k] row-major (k = pw*128 + j): g_B*[o*384 + k]
__device__ __nv_bfloat16 g_Bh[DIM * KTOT];
__device__ __nv_bfloat16 g_Bl[DIM * KTOT];
__device__ float g_Bias[DIM];

// smem buffer layout (per buffer, 1024B-aligned regions):
//   Ah [64][64]bf16 @ 0      (8 KB)
//   Al [64][64]bf16 @ 8192   (8 KB)
//   Bh [128][64]bf16 @ 16384 (16 KB)
//   Bl [128][64]bf16 @ 32768 (16 KB)
#define REG_AL 8192u
#define REG_BH 16384u
#define REG_BL 32768u
#define BUF_STRIDE 49152u
#define SMEM_TOTAL (2 * BUF_STRIDE)

// ---------------- helpers ----------------
__device__ __forceinline__ uint32_t smem_u32(const void* p) {
    uint32_t a;
    asm("{ .reg .u64 t; cvta.to.shared.u64 t, %1; cvt.u32.u64 %0, t; }" : "=r"(a) : "l"(p));
    return a;
}
__device__ __forceinline__ uint32_t swz128(uint32_t off) { return off ^ ((off >> 3) & 0x70); }

#define CP_ASYNC16(dst_u32, src_ptr)                                              \
    asm volatile("{ .reg .u64 g; cvta.to.global.u64 g, %1;\n"                     \
                 "cp.async.cg.shared.global [%0], [g], 16; }"                     \
                 :: "r"(dst_u32), "l"(src_ptr) : "memory")
#define CP_COMMIT() asm volatile("cp.async.commit_group;" ::: "memory")
#define CP_WAIT0()  asm volatile("cp.async.wait_group 0;" ::: "memory")

#define LDSM4(r, addr)                                                            \
    asm volatile("ldmatrix.sync.aligned.m8n8.x4.shared.b16 {%0,%1,%2,%3}, [%4];"  \
                 : "=r"((r)[0]), "=r"((r)[1]), "=r"((r)[2]), "=r"((r)[3])         \
                 : "r"(addr))

#define MMA_BF16(c, A, b0v, b1v)                                                  \
    asm volatile("mma.sync.aligned.m16n8k16.row.col.f32.bf16.bf16.f32 "           \
                 "{%0,%1,%2,%3}, {%4,%5,%6,%7}, {%8,%9}, {%0,%1,%2,%3};"          \
                 : "+f"((c)[0]), "+f"((c)[1]), "+f"((c)[2]), "+f"((c)[3])         \
                 : "r"((A)[0]), "r"((A)[1]), "r"((A)[2]), "r"((A)[3]),            \
                   "r"(b0v), "r"(b1v))

__device__ __forceinline__ uint32_t split_pack2(float a, float b, uint32_t& lo_pack) {
    __nv_bfloat16 ha = __float2bfloat16(a), hb = __float2bfloat16(b);
    __nv_bfloat16 la = __float2bfloat16(a - __bfloat162float(ha));
    __nv_bfloat16 lb = __float2bfloat16(b - __bfloat162float(hb));
    lo_pack = (uint32_t)__bfloat16_as_ushort(la) | ((uint32_t)__bfloat16_as_ushort(lb) << 16);
    return (uint32_t)__bfloat16_as_ushort(ha) | ((uint32_t)__bfloat16_as_ushort(hb) << 16);
}

// ---------------- prologue: split coeff into bf16 hi/lo + bias ----------------
__global__ void prep_kernel(const float* __restrict__ coeff) {
    int bid = blockIdx.x;
    if (bid < 64) {
        int idx = bid * 256 + threadIdx.x;        // edge index [0, 16384)
        int o = idx >> 7, j = idx & 127;
        float4 c = reinterpret_cast<const float4*>(coeff)[idx];
        float v[3] = {c.y, c.z, c.w};             // degrees 1..3
#pragma unroll
        for (int pw = 0; pw < 3; ++pw) {
            float w = v[pw];
            __nv_bfloat16 h = __float2bfloat16(w);
            __nv_bfloat16 l = __float2bfloat16(w - __bfloat162float(h));
            int off = o * KTOT + pw * 128 + j;
            g_Bh[off] = h;
            g_Bl[off] = l;
        }
    } else {
        int wid = threadIdx.x >> 5, lid = threadIdx.x & 31;
        int o = (bid - 64) * 8 + wid;
        float s = 0.f;
#pragma unroll
        for (int t = 0; t < 4; ++t)
            s += coeff[(o * 128 + t * 32 + lid) << 2];
#pragma unroll
        for (int off = 16; off; off >>= 1)
            s += __shfl_xor_sync(0xffffffffu, s, off);
        if (lid == 0) g_Bias[o] = s;
    }
}

// ---------------- main kernel ----------------
__global__ void __launch_bounds__(THREADS, 1)
kan_mma(const float* __restrict__ x, float* __restrict__ out) {
    extern __shared__ char smem[];
    const uint32_t sb = smem_u32(smem);
    const int tid  = threadIdx.x;
    const int lane = tid & 31;
    const int wid  = tid >> 5;
    const int b0   = blockIdx.x * MTILE;

    // staging thread map: row r (0..63), quarter q (0..3) -> 16 consecutive j
    const int sr = tid >> 2;
    const int sq = tid & 3;

    // warp tile coords
    const int m0 = (wid & 1) * 32;
    const int n0 = (wid >> 1) * 32;

    float acc[2][4][4];
#pragma unroll
    for (int mi = 0; mi < 2; ++mi)
#pragma unroll
        for (int nj = 0; nj < 4; ++nj)
#pragma unroll
            for (int i = 0; i < 4; ++i) acc[mi][nj][i] = 0.f;

    float4 xv[4];

    // ---- staging helpers (inlined via lambdas) ----
    auto issue_B = [&](int cn, uint32_t tb) {
#pragma unroll
        for (int i = 0; i < 4; ++i) {
            int idx = tid + i * THREADS;          // 0..1023
            int n = idx >> 3, k8 = idx & 7;
            const __nv_bfloat16* srcH = g_Bh + n * KTOT + cn * KC + k8 * 8;
            const __nv_bfloat16* srcL = g_Bl + n * KTOT + cn * KC + k8 * 8;
            uint32_t sw = swz128((uint32_t)(n * 128 + k8 * 16));
            CP_ASYNC16(sb + tb + REG_BH + sw, srcH);
            CP_ASYNC16(sb + tb + REG_BL + sw, srcL);
        }
    };
    auto issue_X = [&](int cn) {
        const int jhalf = (cn & 1) * 64;
        const float4* xs = reinterpret_cast<const float4*>(
            x + (size_t)(b0 + sr) * DIM + jhalf);
#pragma unroll
        for (int i = 0; i < 4; ++i) xv[i] = xs[sq * 4 + i];
    };
    auto store_A = [&](int cn, uint32_t tb) {
        const int pw = cn >> 1;
        float w[16];
#pragma unroll
        for (int i = 0; i < 4; ++i) {
            w[4 * i + 0] = xv[i].x; w[4 * i + 1] = xv[i].y;
            w[4 * i + 2] = xv[i].z; w[4 * i + 3] = xv[i].w;
        }
        if (pw >= 1) {
#pragma unroll
            for (int i = 0; i < 4; ++i) {
                w[4 * i + 0] *= xv[i].x; w[4 * i + 1] *= xv[i].y;
                w[4 * i + 2] *= xv[i].z; w[4 * i + 3] *= xv[i].w;
            }
        }
        if (pw == 2) {
#pragma unroll
            for (int i = 0; i < 4; ++i) {
                w[4 * i + 0] *= xv[i].x; w[4 * i + 1] *= xv[i].y;
                w[4 * i + 2] *= xv[i].z; w[4 * i + 3] *= xv[i].w;
            }
        }
        uint32_t hp[8], lp[8];
#pragma unroll
        for (int i = 0; i < 8; ++i) hp[i] = split_pack2(w[2 * i], w[2 * i + 1], lp[i]);
        uint32_t base = (uint32_t)(sr * 128 + sq * 32);
        *reinterpret_cast<uint4*>(smem + tb + swz128(base)) =
            make_uint4(hp[0], hp[1], hp[2], hp[3]);
        *reinterpret_cast<uint4*>(smem + tb + swz128(base + 16)) =
            make_uint4(hp[4], hp[5], hp[6], hp[7]);
        *reinterpret_cast<uint4*>(smem + tb + REG_AL + swz128(base)) =
            make_uint4(lp[0], lp[1], lp[2], lp[3]);
        *reinterpret_cast<uint4*>(smem + tb + REG_AL + swz128(base + 16)) =
            make_uint4(lp[4], lp[5], lp[6], lp[7]);
    };

    // ---- prologue: stage chunk 0 ----
    issue_B(0, 0);
    CP_COMMIT();
    issue_X(0);
    store_A(0, 0);
    CP_WAIT0();
    __syncthreads();

    // per-lane ldmatrix addresses (offsets within buffer, before swizzle)
    // A x4: row = m0 + (lane&15) [+ mi*16], kbyte = ks*32 + (lane>>4)*16
    const uint32_t a_row = (uint32_t)(m0 + (lane & 15));
    const uint32_t a_kb  = (uint32_t)((lane >> 4) * 16);
    // B x4: n = n0 + (lane&7) + (lane>>4)*8 [+ ni*16], kbyte = ks*32 + ((lane>>3)&1)*16
    const uint32_t b_row = (uint32_t)(n0 + (lane & 7) + ((lane >> 4) << 3));
    const uint32_t b_kb  = (uint32_t)(((lane >> 3) & 1) * 16);

    for (int c = 0; c < NCHUNK; ++c) {
        const uint32_t tb  = (uint32_t)(c & 1) * BUF_STRIDE;
        const uint32_t tbn = (uint32_t)((c + 1) & 1) * BUF_STRIDE;

        if (c + 1 < NCHUNK) {
            issue_B(c + 1, tbn);
            CP_COMMIT();
            issue_X(c + 1);
        }

        // ---- MMA on buffer tb ----
#pragma unroll
        for (int ks = 0; ks < 4; ++ks) {
            uint32_t ah[2][4], al[2][4], bh[2][4], bl[2][4];
#pragma unroll
            for (int mi = 0; mi < 2; ++mi) {
                uint32_t off = (a_row + mi * 16) * 128 + ks * 32 + a_kb;
                LDSM4(ah[mi], sb + tb + swz128(off));
                LDSM4(al[mi], sb + tb + REG_AL + swz128(off));
            }
#pragma unroll
            for (int ni = 0; ni < 2; ++ni) {
                uint32_t off = (b_row + ni * 16) * 128 + ks * 32 + b_kb;
                LDSM4(bh[ni], sb + tb + REG_BH + swz128(off));
                LDSM4(bl[ni], sb + tb + REG_BL + swz128(off));
            }
#pragma unroll
            for (int mi = 0; mi < 2; ++mi)
#pragma unroll
                for (int nj = 0; nj < 4; ++nj) {
                    const int ni = nj >> 1, br = (nj & 1) * 2;
                    MMA_BF16(acc[mi][nj], ah[mi], bh[ni][br], bh[ni][br + 1]);
                    MMA_BF16(acc[mi][nj], al[mi], bh[ni][br], bh[ni][br + 1]);
                    MMA_BF16(acc[mi][nj], ah[mi], bl[ni][br], bl[ni][br + 1]);
                }
        }

        if (c + 1 < NCHUNK) {
            store_A(c + 1, tbn);
            CP_WAIT0();
        }
        __syncthreads();
    }

    // ---- epilogue: bias + store ----
    float2 bs[4];
#pragma unroll
    for (int nj = 0; nj < 4; ++nj)
        bs[nj] = *reinterpret_cast<const float2*>(g_Bias + n0 + nj * 8 + 2 * (lane & 3));

#pragma unroll
    for (int mi = 0; mi < 2; ++mi) {
        const int r0 = b0 + m0 + mi * 16 + (lane >> 2);
#pragma unroll
        for (int nj = 0; nj < 4; ++nj) {
            const int col = n0 + nj * 8 + 2 * (lane & 3);
            float2 v0 = make_float2(acc[mi][nj][0] + bs[nj].x, acc[mi][nj][1] + bs[nj].y);
            float2 v1 = make_float2(acc[mi][nj][2] + bs[nj].x, acc[mi][nj][3] + bs[nj].y);
            *reinterpret_cast<float2*>(out + (size_t)r0 * DIM + col)       = v0;
            *reinterpret_cast<float2*>(out + (size_t)(r0 + 8) * DIM + col) = v1;
        }
    }
}

// ---------------- launch ----------------
extern "C" void kernel_launch(void* const* d_in, const int* in_sizes, int n_in,
                              void* d_out, int out_size) {
    const float* x     = (const float*)d_in[0];   // [8192, 128] fp32
    const float* coeff = (const float*)d_in[1];   // [16384, 4]  fp32
    float* out = (float*)d_out;                   // [8192, 128] fp32

    cudaFuncSetAttribute(kan_mma, cudaFuncAttributeMaxDynamicSharedMemorySize, SMEM_TOTAL);

    prep_kernel<<<80, 256>>>(coeff);
    kan_mma<<<NCTA, THREADS, SMEM_TOTAL>>>(x, out);
}